// round 7
// baseline (speedup 1.0000x reference)
#include <cuda_runtime.h>

// Problem constants
#define BB   4      // batch
#define CIN  3
#define C1   32     // conv1 out channels (16x16 spatial)
#define C2   64     // conv2 out channels (8x8 spatial)
#define MM   512    // hopfield memory slots
#define DD   64     // token dim (== C2)
#define NTOK 2      // tokens per hopfield block
#define THR  512    // threads per block
#define NBLK 128    // blocks (1 per SM, <= 148 -> all co-resident)
#define LSTR 68     // Lsm row stride (floats): 16B-aligned, conflict-free

// Padded conv1-output layout: [b][ic][18][18] float2 {a1, v1}.
// Halo (1 ring) is NEVER written -> stays zero from static init, so conv2
// needs no bounds checks. Deterministic across graph replays.
#define AVROW 18
#define AVPL  (AVROW*AVROW)     // 324 float2 per (b,ic) plane

// Scratch (allocation-free rule: __device__ globals; zero-initialized)
__device__ float2 g_av[BB*C1*AVPL];   // padded {a1, v1}
__device__ float  g_zq[BB*C2*64];     // masked JVP output (B, C2, 64 spatial)
__device__ float  g_Wc[DD*DD];        // Wv @ Wo (folded projection)
__device__ unsigned g_bar;            // cumulative grid-barrier ticket counter

// Software grid barrier: all NBLK blocks co-resident (1 block/SM). Cumulative
// tickets stay NBLK-aligned across graph replays (2 barriers * 128 arrivals
// per launch; 2^32 % 128 == 0 so wrap is safe).
__device__ __forceinline__ void grid_barrier() {
    __syncthreads();
    if (threadIdx.x == 0) {
        __threadfence();
        unsigned ticket = atomicAdd(&g_bar, 1u);
        unsigned target = (ticket & ~(unsigned)(NBLK - 1)) + NBLK;
        while ((int)(*(volatile unsigned*)&g_bar - target) < 0) { }
        __threadfence();
    }
    __syncthreads();
}

// Shared memory layout (float offsets)
#define LSM_OFF   0                       // 512*68 = 34816
#define WCS_OFF   34816                   // 64*64  = 4096
#define PS2_OFF   38912                   // 512 float2 = 1024 f
#define PART2_OFF 39936                   // 512 float2 = 1024 f
#define TS_OFF    40960                   // 128 f
#define OS2_OFF   41088                   // 64 float2 = 128 f
#define RED2_OFF  41216                   // 20 float2 = 40 f
#define XPAD_OFF  41256                   // 3*34*34 = 3468 f (16B aligned)
#define SMEM_FLOATS (XPAD_OFF + 3*34*34)  // 44724 floats = 178896 B

__global__ __launch_bounds__(THR, 1)
void fused_kernel(const float* __restrict__ x,
                  const float* __restrict__ w1,
                  const float* __restrict__ b1,
                  const float* __restrict__ w2,
                  const float* __restrict__ b2,
                  const float* __restrict__ lookup,
                  const float* __restrict__ Wv,
                  const float* __restrict__ Wo,
                  float* __restrict__ out) {
    extern __shared__ float smem[];
    float*  Lsm   = smem + LSM_OFF;
    float*  WcS   = smem + WCS_OFF;
    float2* pS2   = (float2*)(smem + PS2_OFF);
    float2* part2 = (float2*)(smem + PART2_OFF);
    float*  tS    = smem + TS_OFF;
    float2* oS2   = (float2*)(smem + OS2_OFF);
    float2* red2  = (float2*)(smem + RED2_OFF);
    float*  xpad  = smem + XPAD_OFF;      // [3][34][34] zero-padded

    int tid  = threadIdx.x;
    int lane = tid & 31;
    int wid  = tid >> 5;
    int blk  = blockIdx.x;
    int gtid = blk * THR + tid;

    // ===== Phase 0a: zero the padded x tile =================================
    for (int i = tid; i < 3*34*34; i += THR) xpad[i] = 0.f;
    __syncthreads();

    // ===== Phase 0b: stage lookup -> Lsm  and  x[b] -> xpad interior ========
    {
        const float4* L4   = (const float4*)lookup;
        float4*       Lsm4 = (float4*)Lsm;         // row stride 17 float4
        #pragma unroll
        for (int batch = 0; batch < 2; batch++) {
            float4 v[8];
            #pragma unroll
            for (int u = 0; u < 8; u++)
                v[u] = __ldg(&L4[(batch*8 + u)*THR + tid]);
            #pragma unroll
            for (int u = 0; u < 8; u++) {
                int f = (batch*8 + u)*THR + tid;   // float4 index
                Lsm4[(f >> 4)*17 + (f & 15)] = v[u];
            }
        }
    }
    {
        int cb = blk >> 5;                         // this block's batch sample
        const float* xb = x + cb * CIN * 1024;
        #pragma unroll
        for (int it = 0; it < 6; it++) {
            int i = it*THR + tid;                  // < 3072
            int ic = i >> 10, r = (i >> 5) & 31, c = i & 31;
            xpad[(ic*34 + r + 1)*34 + c + 1] = __ldg(&xb[i]);
        }
    }
    __syncthreads();

    // ===== Phase 1: conv1 from padded smem (branch-free) + Wc ==============
    {
        int cb   = blk >> 5;        // batch
        int oc   = blk & 31;        // conv1 out channel (one per block)
        int o    = tid >> 1;        // output 0..255
        int half = tid & 1;         // ky half {0,1} vs {2,3}
        int oy = o >> 4, ox = o & 15;

        float s = 0.f;
        #pragma unroll
        for (int ic = 0; ic < CIN; ic++) {
            const float* xp = &xpad[ic*34*34];
            const float* wp = &w1[(oc*CIN + ic)*16];
            #pragma unroll
            for (int kk = 0; kk < 2; kk++) {
                int ky = half*2 + kk;
                const float* row = &xp[(oy*2 + ky)*34 + ox*2];
                #pragma unroll
                for (int kx = 0; kx < 4; kx++)
                    s += row[kx] * __ldg(&wp[ky*4 + kx]);
            }
        }
        s += __shfl_xor_sync(0xFFFFFFFFu, s, 1);
        if (half == 0) {
            float pre = s + b1[oc];
            bool on = pre > 0.f;
            g_av[(cb*C1 + oc)*AVPL + (oy + 1)*AVROW + (ox + 1)] =
                make_float2(on ? pre : 0.f, on ? s : 0.f);
        }
        // Wc = Wv @ Wo: 4096 elems, 32 per block (threads 0..31)
        if (tid < 32) {
            int i = blk*32 + tid;
            int d = i >> 6, e = i & 63;
            float ws = 0.f;
            #pragma unroll 16
            for (int k = 0; k < DD; k++)
                ws += __ldg(&Wv[d*DD + k]) * __ldg(&Wo[k*DD + e]);
            g_Wc[i] = ws;
        }
    }
    grid_barrier();

    // ===== Phase 2: conv2 from padded gmem (branch-free), ic split 4 =======
    {
        int h  = gtid & 3;           // ic quarter
        int p  = gtid >> 2;          // output index, < 16384
        int ox = p & 7;
        int oy = (p >> 3) & 7;
        int oc = (p >> 6) & 63;
        int cb = p >> 12;

        float sA = 0.f, sV = 0.f;
        int ic0 = h * 8;
        #pragma unroll 2
        for (int ic = ic0; ic < ic0 + 8; ic++) {
            const float2* avp = &g_av[(cb*C1 + ic)*AVPL];
            const float4* wp4 = (const float4*)&w2[(oc*C1 + ic)*16];
            #pragma unroll
            for (int ky = 0; ky < 4; ky++) {
                float4 w4 = __ldg(&wp4[ky]);
                const float2* row = &avp[(oy*2 + ky)*AVROW + ox*2];
                float2 a0 = __ldg(&row[0]);
                float2 a1 = __ldg(&row[1]);
                float2 a2 = __ldg(&row[2]);
                float2 a3 = __ldg(&row[3]);
                sA += a0.x*w4.x + a1.x*w4.y + a2.x*w4.z + a3.x*w4.w;
                sV += a0.y*w4.x + a1.y*w4.y + a2.y*w4.z + a3.y*w4.w;
            }
        }
        sA += __shfl_xor_sync(0xFFFFFFFFu, sA, 1);
        sV += __shfl_xor_sync(0xFFFFFFFFu, sV, 1);
        sA += __shfl_xor_sync(0xFFFFFFFFu, sA, 2);
        sV += __shfl_xor_sync(0xFFFFFFFFu, sV, 2);
        if (h == 0) {
            float pre = sA + b2[oc];
            g_zq[(cb*C2 + oc)*64 + (oy*8 + ox)] = (pre > 0.f) ? sV : 0.f;
        }
    }
    grid_barrier();

    // ===== Phase 3: hopfield ===============================================
    int n0 = (blk & 31) * NTOK;
    int b  = blk >> 5;

    {
        const float4* W4 = (const float4*)g_Wc;
        ((float4*)WcS)[tid]       = __ldg(&W4[tid]);
        ((float4*)WcS)[tid + THR] = __ldg(&W4[tid + THR]);
    }
    if (tid < DD*NTOK) {
        int j = tid & 1, d = tid >> 1;
        tS[d*NTOK + j] = g_zq[(b*C2 + d)*64 + n0 + j];
    }
    __syncthreads();

    // --- scores: thread owns row m = tid, 2 tokens ---
    float a0 = 0.f, a1 = 0.f;
    {
        const float4* lrow = (const float4*)&Lsm[tid*LSTR];
        #pragma unroll
        for (int q = 0; q < 16; q++) {
            float4 l  = lrow[q];
            float4 t0 = *(const float4*)&tS[q*8];
            float4 t1 = *(const float4*)&tS[q*8 + 4];
            a0 += l.x*t0.x + l.y*t0.z + l.z*t1.x + l.w*t1.z;
            a1 += l.x*t0.y + l.y*t0.w + l.z*t1.y + l.w*t1.w;
        }
    }
    a0 *= 0.125f; a1 *= 0.125f;   // 1/sqrt(64)

    // --- block max ---
    {
        float mx0 = a0, mx1 = a1;
        #pragma unroll
        for (int o = 16; o > 0; o >>= 1) {
            mx0 = fmaxf(mx0, __shfl_xor_sync(0xFFFFFFFFu, mx0, o));
            mx1 = fmaxf(mx1, __shfl_xor_sync(0xFFFFFFFFu, mx1, o));
        }
        if (lane == 0) red2[wid] = make_float2(mx0, mx1);
    }
    __syncthreads();
    if (tid < 32) {
        float2 v = (lane < 16) ? red2[lane] : make_float2(-1e30f, -1e30f);
        #pragma unroll
        for (int o = 8; o > 0; o >>= 1) {
            v.x = fmaxf(v.x, __shfl_xor_sync(0xFFFFFFFFu, v.x, o));
            v.y = fmaxf(v.y, __shfl_xor_sync(0xFFFFFFFFu, v.y, o));
        }
        if (lane == 0) red2[16] = v;
    }
    __syncthreads();
    float2 MX = red2[16];

    // --- exp + block sum ---
    float e0 = __expf(a0 - MX.x);
    float e1 = __expf(a1 - MX.y);
    pS2[tid] = make_float2(e0, e1);
    {
        float s0 = e0, s1 = e1;
        #pragma unroll
        for (int o = 16; o > 0; o >>= 1) {
            s0 += __shfl_xor_sync(0xFFFFFFFFu, s0, o);
            s1 += __shfl_xor_sync(0xFFFFFFFFu, s1, o);
        }
        if (lane == 0) red2[wid] = make_float2(s0, s1);
    }
    __syncthreads();
    if (tid < 32) {
        float2 v = (lane < 16) ? red2[lane] : make_float2(0.f, 0.f);
        #pragma unroll
        for (int o = 8; o > 0; o >>= 1) {
            v.x += __shfl_xor_sync(0xFFFFFFFFu, v.x, o);
            v.y += __shfl_xor_sync(0xFFFFFFFFu, v.y, o);
        }
        if (lane == 0) red2[17] = v;
    }
    __syncthreads();
    float2 SUM = red2[17];

    // --- retrieval: part[c][d] = sum over 64 m of p[m]*L[m][d] ---
    {
        int d = tid & 63, c = tid >> 6;   // 8 chunks of 64 m
        float r0 = 0.f, r1 = 0.f;
        int m0 = c * 64;
        #pragma unroll 8
        for (int mm = 0; mm < 64; mm++) {
            float2 p = pS2[m0 + mm];              // broadcast
            float  l = Lsm[(m0 + mm)*LSTR + d];   // conflict-free
            r0 += p.x*l; r1 += p.y*l;
        }
        part2[c*64 + d] = make_float2(r0, r1);
    }
    __syncthreads();
    if (tid < NTOK*DD) {
        int j = tid >> 6, d = tid & 63;
        const float* pf = (const float*)part2;
        float s = 0.f;
        #pragma unroll
        for (int c = 0; c < 8; c++)
            s += pf[(c*64 + d)*2 + j];
        float inv = 1.f / (j ? SUM.y : SUM.x);
        tS[j*DD + d] = s * inv;                   // reuse tS as tmp[j][d]
    }
    __syncthreads();

    // --- projection: out[j][e] = sum_d tmp[j][d] * Wc[d][e] ---
    if (tid < NTOK*DD) {
        int j = tid >> 6, e = tid & 63;
        float o = 0.f;
        const float* tp = &tS[j*DD];
        #pragma unroll 16
        for (int d = 0; d < DD; d++)
            o += tp[d] * WcS[d*DD + e];           // bcast + conflict-free
        ((float*)&oS2[e])[j] = o;
    }
    __syncthreads();
    if (tid < DD) {
        float2 ov = oS2[tid];
        *(float2*)&out[(b*C2 + tid)*64 + n0] = ov;
    }
}

// ---------------------------------------------------------------------------
extern "C" void kernel_launch(void* const* d_in, const int* in_sizes, int n_in,
                              void* d_out, int out_size) {
    const float* x       = (const float*)d_in[0];
    const float* conv1_w = (const float*)d_in[1];
    const float* conv1_b = (const float*)d_in[2];
    const float* conv2_w = (const float*)d_in[3];
    const float* conv2_b = (const float*)d_in[4];
    const float* lookup  = (const float*)d_in[5];
    const float* Wv      = (const float*)d_in[6];
    const float* Wo      = (const float*)d_in[7];
    float* out = (float*)d_out;

    const size_t smem_bytes = SMEM_FLOATS * sizeof(float);

    cudaFuncSetAttribute(fused_kernel,
                         cudaFuncAttributeMaxDynamicSharedMemorySize,
                         (int)smem_bytes);
    cudaFuncSetAttribute(fused_kernel,
                         cudaFuncAttributePreferredSharedMemoryCarveout, 100);

    fused_kernel<<<NBLK, THR, smem_bytes>>>(
        x, conv1_w, conv1_b, conv2_w, conv2_b, lookup, Wv, Wo, out);
}